// round 3
// baseline (speedup 1.0000x reference)
#include <cuda_runtime.h>
#include <math.h>
#include <stdint.h>

#define BB 64
#define CC 64
#define NXX 128
#define NYY 128
#define SS (NXX*NYY)
#define MM1 12
#define MM2 12
#define KXN 24
#define NMODE (KXN*MM2)   /* 288 */
#define NTT 50
#define LWSTRIDE (64*64*144) /* spectral weight elements per layer */

/* ------------ scratch (static device memory; no allocation) ------------ */
__device__ float  g_x[BB*CC*SS];              /* 268MB activation, in-place across layers */
__device__ float  g_sparse[BB*SS];
__device__ float  g_counts[BB*SS];
__device__ float  g_grid[BB*SS];
__device__ float2 g_Ty[BB*CC*NXX*MM2];        /* y-DFT result */
__device__ float2 g_modes[BB*CC*NMODE];
__device__ float2 g_omodes[BB*CC*NMODE];
__device__ float2 g_U[BB*CC*NXX*MM2];         /* inverse-x result */
__device__ float2 g_By[MM2*NYY];              /* (cos,sin) 2*pi*ky*y/128 */
__device__ float2 g_Bx[KXN*NXX];              /* (cos,sin) 2*pi*kx*x/128, kx mapped */

__device__ __forceinline__ float gelu_f(float v){
    return 0.5f*v*(1.0f+erff(v*0.70710678118654752440f));
}

/* ------------ basis tables (double-precision twiddles) ------------ */
__global__ void k_basis(){
    int t = threadIdx.x;
    for(int i=t;i<MM2*NYY;i+=blockDim.x){
        int ky=i>>7, y=i&127;
        int m=(ky*y)&127;
        double a=(double)m*(6.283185307179586476925286766559/128.0);
        g_By[i]=make_float2((float)cos(a),(float)sin(a));
    }
    for(int i=t;i<KXN*NXX;i+=blockDim.x){
        int kx=i>>7, x=i&127;
        int kg = kx<12 ? kx : kx+104;   /* 12..23 -> 116..127 */
        int m=(kg*x)&127;
        double a=(double)m*(6.283185307179586476925286766559/128.0);
        g_Bx[i]=make_float2((float)cos(a),(float)sin(a));
    }
}

/* ------------ sparse Voronoi-ish grid ------------ */
__global__ void k_zero(){
    int i = blockIdx.x*blockDim.x+threadIdx.x;
    if(i<BB*SS){ g_sparse[i]=0.f; g_counts[i]=0.f; }
}

__global__ void k_scatter(const float* __restrict__ xyt, const float* __restrict__ oc,
                          const float* __restrict__ ov, const int* __restrict__ nb,
                          const int* __restrict__ siy, const int* __restrict__ six){
    int b = threadIdx.x;
    if(b>=BB) return;
    float tq = xyt[b*3+2];
    float* sp = g_sparse + (size_t)b*SS;
    float* ct = g_counts + (size_t)b*SS;
    for(int k=0;k<64;k++){
        int idx = nb[b*64+k];
        int sid = idx / NTT;
        float tt = oc[idx*3+2];
        float w = expf(-0.1f*fabsf(tt-tq));
        float v = ov[idx]*w;
        int lin = siy[sid]*NYY + six[sid];
        sp[lin]+=v; ct[lin]+=w;
    }
}

__global__ void k_grid(){
    int i = blockIdx.x*blockDim.x+threadIdx.x;
    if(i<BB*SS){
        float c=g_counts[i];
        g_grid[i] = (c>0.f) ? g_sparse[i]/fmaxf(c,1e-6f) : 0.f;
    }
}

/* ------------ fc0: 3 -> 64 channels ------------ */
__global__ void k_fc0(const float* __restrict__ xg, const float* __restrict__ yg,
                      const float* __restrict__ w, const float* __restrict__ bias){
    int i = blockIdx.x*blockDim.x+threadIdx.x;   /* < BB*CC*SS */
    int s = i & (SS-1);
    int wc = (i>>14)&63;
    int b = i>>20;
    float g = g_grid[b*SS+s];
    g_x[i] = g*w[wc] + xg[s]*w[64+wc] + yg[s]*w[128+wc] + bias[wc];
}

/* ------------ K1: rDFT along y to 12 modes ------------ */
__global__ void k1_dfty(){
    __shared__ float  sx[32*129];
    __shared__ float2 sb[12*129];
    int bid = blockIdx.x;
    int bc = bid>>2, xq = bid&3;
    const float* xp = g_x + (size_t)bc*SS + xq*32*NYY;
    for(int i=threadIdx.x;i<32*128;i+=384){ int r=i>>7,y=i&127; sx[r*129+y]=xp[i]; }
    for(int i=threadIdx.x;i<12*128;i+=384){ int ky=i>>7,y=i&127; sb[ky*129+y]=g_By[i]; }
    __syncthreads();
    int r = threadIdx.x/12;
    int ky = threadIdx.x - r*12;
    float are=0.f, aim=0.f;
    #pragma unroll 4
    for(int y=0;y<128;y++){
        float v = sx[r*129+y];
        float2 e = sb[ky*129+y];
        are += v*e.x;     /* e^{-i}: re = +v*cos */
        aim -= v*e.y;     /*         im = -v*sin */
    }
    int x = xq*32+r;
    g_Ty[((size_t)bc*128+x)*12+ky] = make_float2(are,aim);
}

/* ------------ K2: DFT along x at 24 selected modes ------------ */
__global__ void k2_dftx(){
    __shared__ float2 sT[128*12];
    __shared__ float2 sb[24*129];
    int bc = blockIdx.x;
    const float2* tp = g_Ty + (size_t)bc*1536;
    for(int i=threadIdx.x;i<1536;i+=288) sT[i]=tp[i];
    for(int i=threadIdx.x;i<24*128;i+=288){ int kx=i>>7,x=i&127; sb[kx*129+x]=g_Bx[i]; }
    __syncthreads();
    int kx = threadIdx.x/12;
    int ky = threadIdx.x - kx*12;
    float are=0.f, aim=0.f;
    #pragma unroll 4
    for(int x=0;x<128;x++){
        float2 t = sT[x*12+ky];
        float2 e = sb[kx*129+x];     /* multiply by (c - i s) */
        are += t.x*e.x + t.y*e.y;
        aim += t.y*e.x - t.x*e.y;
    }
    g_modes[(size_t)bc*NMODE + kx*12 + ky] = make_float2(are,aim);
}

/* ------------ K3: per-mode complex 64x64 channel mix ------------ */
__global__ void k3_specmul(const float* __restrict__ w1r, const float* __restrict__ w1i,
                           const float* __restrict__ w2r, const float* __restrict__ w2i){
    __shared__ float2 sW[4096];   /* [i*64+o] */
    __shared__ float2 sM[2048];   /* [bl*64+i] */
    int m  = blockIdx.x>>1;
    int bh = blockIdx.x&1;
    int kx = m/12, ky = m - kx*12;
    const float *wr, *wi; int kxw;
    if(kx<12){ wr=w1r; wi=w1i; kxw=kx; } else { wr=w2r; wi=w2i; kxw=kx-12; }
    int wofs = kxw*12+ky;
    for(int i=threadIdx.x;i<4096;i+=256)
        sW[i] = make_float2(wr[i*144+wofs], wi[i*144+wofs]);
    for(int i=threadIdx.x;i<2048;i+=256){
        int bl=i>>6, c=i&63;
        sM[i] = g_modes[((size_t)((bh*32+bl)*64+c))*NMODE + m];
    }
    __syncthreads();
    for(int k=0;k<8;k++){
        int idx = threadIdx.x + k*256;
        int bl = idx>>6, o = idx&63;
        float are=0.f, aim=0.f;
        #pragma unroll 4
        for(int i=0;i<64;i++){
            float2 mv=sM[bl*64+i];
            float2 wv=sW[i*64+o];
            are += mv.x*wv.x - mv.y*wv.y;
            aim += mv.x*wv.y + mv.y*wv.x;
        }
        g_omodes[((size_t)((bh*32+bl)*64+o))*NMODE + m] = make_float2(are,aim);
    }
}

/* ------------ K4: inverse DFT along x (scale & ky-weight folded in) ------------ */
__global__ void k4_invx(){
    __shared__ float2 sO[288];
    __shared__ float2 sb[24*129];
    int bc = blockIdx.x;
    const float2* op = g_omodes + (size_t)bc*NMODE;
    for(int i=threadIdx.x;i<288;i+=384) sO[i]=op[i];
    for(int i=threadIdx.x;i<24*128;i+=384){ int kx=i>>7,x=i&127; sb[kx*129+x]=g_Bx[i]; }
    __syncthreads();
    int xb = threadIdx.x/12;
    int ky = threadIdx.x - xb*12;
    float scale = (ky==0 ? 1.f : 2.f)*(1.f/16384.f);
    for(int j=0;j<4;j++){
        int x = xb + 32*j;
        float are=0.f, aim=0.f;
        #pragma unroll
        for(int kx=0;kx<24;kx++){
            float2 o = sO[kx*12+ky];
            float2 e = sb[kx*129+x];  /* e^{+i}: (c, s) */
            are += o.x*e.x - o.y*e.y;
            aim += o.x*e.y + o.y*e.x;
        }
        g_U[((size_t)bc*128+x)*12+ky] = make_float2(are*scale, aim*scale);
    }
}

/* ------------ K5: fused inverse-y DFT + 64x64 pointwise + bias + GELU, in-place ------------ */
extern __shared__ float smem5[];
__global__ void k5_pw(const float* __restrict__ pw, const float* __restrict__ pwb){
    float4* sX  = (float4*)smem5;            /* 64 x 32 float4  (x tile, y packed) */
    float*  sW  = (float*)(sX + 2048);       /* 4096 : [o*64+c] */
    float2* sU  = (float2*)(sW + 4096);      /* 768  : [o*12+ky] */
    float*  sBc = (float*)(sU + 768);        /* 1536 */
    float*  sBs = sBc + 1536;                /* 1536 */

    int b = blockIdx.x>>7;
    int x = blockIdx.x&127;

    for(int i=threadIdx.x;i<2048;i+=256){
        int c=i>>5, yq=i&31;
        const float4* src = (const float4*)(g_x + ((((size_t)(b*64+c))*128+x)<<7));
        sX[c*32+yq] = src[yq];
    }
    for(int i=threadIdx.x;i<4096;i+=256) sW[i]=pw[i];
    for(int i=threadIdx.x;i<768;i+=256){
        int o=i/12, ky=i-o*12;
        sU[i] = g_U[(((size_t)(b*64+o))*128+x)*12 + ky];
    }
    for(int i=threadIdx.x;i<1536;i+=256){
        float2 e=g_By[i]; sBc[i]=e.x; sBs[i]=e.y;
    }
    __syncthreads();

    int yq = threadIdx.x & 31;
    int og = threadIdx.x >> 5;     /* 0..7 */
    for(int rep=0;rep<2;rep++){
        int o0 = (og + rep*8)*4;
        float acc[4][4];
        #pragma unroll
        for(int oi=0;oi<4;oi++){
            float bs = pwb[o0+oi];
            acc[oi][0]=bs; acc[oi][1]=bs; acc[oi][2]=bs; acc[oi][3]=bs;
        }
        #pragma unroll 4
        for(int c=0;c<64;c++){
            float4 xv = sX[c*32+yq];
            #pragma unroll
            for(int oi=0;oi<4;oi++){
                float w = sW[(o0+oi)*64+c];
                acc[oi][0]+=w*xv.x; acc[oi][1]+=w*xv.y;
                acc[oi][2]+=w*xv.z; acc[oi][3]+=w*xv.w;
            }
        }
        #pragma unroll
        for(int ky=0;ky<12;ky++){
            float4 cb = ((float4*)sBc)[ky*32+yq];
            float4 sb = ((float4*)sBs)[ky*32+yq];
            #pragma unroll
            for(int oi=0;oi<4;oi++){
                float2 u = sU[(o0+oi)*12+ky];
                acc[oi][0]+= u.x*cb.x - u.y*sb.x;
                acc[oi][1]+= u.x*cb.y - u.y*sb.y;
                acc[oi][2]+= u.x*cb.z - u.y*sb.z;
                acc[oi][3]+= u.x*cb.w - u.y*sb.w;
            }
        }
        #pragma unroll
        for(int oi=0;oi<4;oi++){
            float4 outv;
            outv.x = gelu_f(acc[oi][0]);
            outv.y = gelu_f(acc[oi][1]);
            outv.z = gelu_f(acc[oi][2]);
            outv.w = gelu_f(acc[oi][3]);
            float4* dst = (float4*)(g_x + ((((size_t)(b*64+o0+oi))*128+x)<<7));
            dst[yq] = outv;
        }
    }
}

/* ------------ final: layer-3 point eval + fc1 + fc2 + bilinear ------------ */
__global__ void k_final(const float* __restrict__ xyt,
                        const float* __restrict__ pw, const float* __restrict__ pwb,
                        const float* __restrict__ fc1w, const float* __restrict__ fc1b,
                        const float* __restrict__ fc2w, const float* __restrict__ fc2b,
                        const int* __restrict__ Lxp, const int* __restrict__ Lyp,
                        float* __restrict__ out){
    __shared__ float  sXv[64];
    __shared__ float2 sPh[288];
    __shared__ float  sPart[128];
    __shared__ float  sY3[64];
    __shared__ float  sH[128];
    int b = blockIdx.x;
    int t = threadIdx.x;

    int rlx = Lxp[0], rly = Lyp[0];
    float Lx = (rlx>0 && rlx<(1<<23)) ? (float)rlx : __int_as_float(rlx);
    float Ly = (rly>0 && rly<(1<<23)) ? (float)rly : __int_as_float(rly);
    float qx = xyt[b*3+0], qy = xyt[b*3+1];
    float x01 = fminf(fmaxf(qx/fmaxf(Lx,1e-6f),0.f),1.f);
    float y01 = fminf(fmaxf(qy/fmaxf(Ly,1e-6f),0.f),1.f);
    float gx = x01*127.f, gy = y01*127.f;
    int x0 = (int)floorf(gx), y0 = (int)floorf(gy);
    int x1 = min(x0+1,127),  y1 = min(y0+1,127);
    float wx = gx-(float)x0, wy = gy-(float)y0;

    float outAcc = 0.f;   /* meaningful for t<3 */

    for(int p=0;p<4;p++){
        int ix = p&1, iy = p>>1;
        int px = ix? x1:x0;
        int py = iy? y1:y0;
        float wgt = (ix? wx : 1.f-wx)*(iy? wy : 1.f-wy);

        for(int m=t;m<288;m+=128){
            int kx=m/12, ky=m-kx*12;
            int kg = kx<12 ? kx : kx+104;
            int mm = (kg*px + ky*py)&127;
            float a = (float)mm*(6.2831853071795864769f/128.f);
            float sv,cv; sincosf(a,&sv,&cv);
            float sc = (ky==0?1.f:2.f)*(1.f/16384.f);
            sPh[m] = make_float2(cv*sc, sv*sc);
        }
        if(t<64) sXv[t] = g_x[((((size_t)(b*64+t))*128+px)<<7)+py];
        __syncthreads();
        {
            int o = t&63, h = t>>6;
            const float2* op = g_omodes + (size_t)(b*64+o)*288 + h*144;
            const float2* ph = sPh + h*144;
            float acc=0.f;
            #pragma unroll 4
            for(int m=0;m<144;m++){
                float2 z=op[m]; float2 e=ph[m];
                acc += z.x*e.x - z.y*e.y;   /* Re(z * e^{+i}) */
            }
            sPart[t]=acc;
        }
        __syncthreads();
        if(t<64){
            float v = sPart[t]+sPart[t+64];
            float a = pwb[t];
            #pragma unroll 4
            for(int c=0;c<64;c++) a += sXv[c]*pw[t*64+c];
            sY3[t] = v + a;   /* layer 3: no gelu */
        }
        __syncthreads();
        {
            float a = fc1b[t];
            #pragma unroll 4
            for(int o=0;o<64;o++) a += sY3[o]*fc1w[o*128+t];
            sH[t] = gelu_f(a);
        }
        __syncthreads();
        if(t<3){
            float a = fc2b[t];
            #pragma unroll 4
            for(int f=0;f<128;f++) a += sH[f]*fc2w[f*3+t];
            outAcc += wgt*a;
        }
        __syncthreads();
    }
    if(t<3) out[b*3+t]=outAcc;
}

/* ------------ launch ------------ */
extern "C" void kernel_launch(void* const* d_in, const int* in_sizes, int n_in,
                              void* d_out, int out_size){
    const float* xyt   = (const float*)d_in[0];
    const float* oc    = (const float*)d_in[1];
    const float* ov    = (const float*)d_in[2];
    const float* xg    = (const float*)d_in[3];
    const float* yg    = (const float*)d_in[4];
    const float* fc0w  = (const float*)d_in[5];
    const float* fc0b  = (const float*)d_in[6];
    const float* w1r   = (const float*)d_in[7];
    const float* w1i   = (const float*)d_in[8];
    const float* w2r   = (const float*)d_in[9];
    const float* w2i   = (const float*)d_in[10];
    const float* pww   = (const float*)d_in[11];
    const float* pwb   = (const float*)d_in[12];
    const float* fc1w  = (const float*)d_in[13];
    const float* fc1b  = (const float*)d_in[14];
    const float* fc2w  = (const float*)d_in[15];
    const float* fc2b  = (const float*)d_in[16];
    const int*   nb    = (const int*)d_in[17];
    const int*   siy   = (const int*)d_in[18];
    const int*   six   = (const int*)d_in[19];
    const int*   Lxp   = (const int*)d_in[20];
    const int*   Lyp   = (const int*)d_in[21];
    float* out = (float*)d_out;

    cudaFuncSetAttribute(k5_pw, cudaFuncAttributeMaxDynamicSharedMemorySize, 67584);

    k_basis<<<1,256>>>();
    k_zero<<<(BB*SS)/256,256>>>();
    k_scatter<<<1,64>>>(xyt,oc,ov,nb,siy,six);
    k_grid<<<(BB*SS)/256,256>>>();
    k_fc0<<<(BB*CC*SS)/256,256>>>(xg,yg,fc0w,fc0b);

    for(int L=0;L<4;L++){
        k1_dfty<<<BB*CC*4,384>>>();
        k2_dftx<<<BB*CC,288>>>();
        k3_specmul<<<NMODE*2,256>>>(w1r+(size_t)L*LWSTRIDE, w1i+(size_t)L*LWSTRIDE,
                                    w2r+(size_t)L*LWSTRIDE, w2i+(size_t)L*LWSTRIDE);
        if(L<3){
            k4_invx<<<BB*CC,384>>>();
            k5_pw<<<BB*NXX,256,67584>>>(pww+(size_t)L*4096, pwb+(size_t)L*64);
        }
    }
    k_final<<<BB,128>>>(xyt, pww+3*4096, pwb+3*64,
                        fc1w, fc1b, fc2w, fc2b, Lxp, Lyp, out);
}

// round 4
// speedup vs baseline: 1.2323x; 1.2323x over previous
#include <cuda_runtime.h>
#include <math.h>
#include <stdint.h>

#define BB 64
#define CC 64
#define NXX 128
#define NYY 128
#define SS (NXX*NYY)
#define MM2 12
#define KXN 24
#define NMODE (KXN*MM2)   /* 288 */
#define NTT 50
#define LWSTRIDE (64*64*144)

#define APITCH 100   /* sA pitch (floats) */
#define BPITCH 136   /* sB / out tile pitch */
#define DPITCH 132   /* k1 standalone A pitch */
#define B2PITCH 40   /* forward-DFT basis pitch */

/* ------------ scratch ------------ */
__device__ float  g_x[BB*CC*SS];
__device__ float  g_sparse[BB*SS];
__device__ float  g_counts[BB*SS];
__device__ float  g_grid[BB*SS];
__device__ float2 g_Ty[BB*CC*NXX*MM2];
__device__ float2 g_modes[BB*CC*NMODE];
__device__ float2 g_omodes[BB*CC*NMODE];
__device__ float2 g_U[BB*CC*NXX*MM2];
__device__ float2 g_By[MM2*NYY];
__device__ float2 g_Bx[KXN*NXX];

extern __shared__ float sm[];

__device__ __forceinline__ float gelu_f(float v){
    return 0.5f*v*(1.0f+erff(v*0.70710678118654752440f));
}
__device__ __forceinline__ unsigned f2tf(float f){
    unsigned r; asm("cvt.rna.tf32.f32 %0, %1;" : "=r"(r) : "f"(f)); return r;
}
__device__ __forceinline__ void mma_tf32(float c[4],
        unsigned a0,unsigned a1,unsigned a2,unsigned a3,
        unsigned b0,unsigned b1){
    asm("mma.sync.aligned.m16n8k8.row.col.f32.tf32.tf32.f32 "
        "{%0,%1,%2,%3}, {%4,%5,%6,%7}, {%8,%9}, {%0,%1,%2,%3};"
        : "+f"(c[0]),"+f"(c[1]),"+f"(c[2]),"+f"(c[3])
        : "r"(a0),"r"(a1),"r"(a2),"r"(a3),"r"(b0),"r"(b1));
}

/* ------------ basis tables ------------ */
__global__ void k_basis(){
    int t = threadIdx.x;
    for(int i=t;i<MM2*NYY;i+=blockDim.x){
        int ky=i>>7, y=i&127;
        int m=(ky*y)&127;
        double a=(double)m*(6.283185307179586476925286766559/128.0);
        g_By[i]=make_float2((float)cos(a),(float)sin(a));
    }
    for(int i=t;i<KXN*NXX;i+=blockDim.x){
        int kx=i>>7, x=i&127;
        int kg = kx<12 ? kx : kx+104;
        int m=(kg*x)&127;
        double a=(double)m*(6.283185307179586476925286766559/128.0);
        g_Bx[i]=make_float2((float)cos(a),(float)sin(a));
    }
}

/* ------------ sparse grid ------------ */
__global__ void k_zero(){
    int i = blockIdx.x*blockDim.x+threadIdx.x;
    if(i<BB*SS){ g_sparse[i]=0.f; g_counts[i]=0.f; }
}
__global__ void k_scatter(const float* __restrict__ xyt, const float* __restrict__ oc,
                          const float* __restrict__ ov, const int* __restrict__ nb,
                          const int* __restrict__ siy, const int* __restrict__ six){
    int b = threadIdx.x;
    if(b>=BB) return;
    float tq = xyt[b*3+2];
    float* sp = g_sparse + (size_t)b*SS;
    float* ct = g_counts + (size_t)b*SS;
    for(int k=0;k<64;k++){
        int idx = nb[b*64+k];
        int sid = idx / NTT;
        float tt = oc[idx*3+2];
        float w = expf(-0.1f*fabsf(tt-tq));
        float v = ov[idx]*w;
        int lin = siy[sid]*NYY + six[sid];
        sp[lin]+=v; ct[lin]+=w;
    }
}
__global__ void k_grid(){
    int i = blockIdx.x*blockDim.x+threadIdx.x;
    if(i<BB*SS){
        float c=g_counts[i];
        g_grid[i] = (c>0.f) ? g_sparse[i]/fmaxf(c,1e-6f) : 0.f;
    }
}

/* ------------ fc0 ------------ */
__global__ void k_fc0(const float* __restrict__ xg, const float* __restrict__ yg,
                      const float* __restrict__ w, const float* __restrict__ bias){
    int i = blockIdx.x*blockDim.x+threadIdx.x;
    int s = i & (SS-1);
    int wc = (i>>14)&63;
    int b = i>>20;
    float g = g_grid[b*SS+s];
    g_x[i] = g*w[wc] + xg[s]*w[64+wc] + yg[s]*w[128+wc] + bias[wc];
}

/* ------------ shared forward-y-DFT GEMM (M=64 rows, N=24, K=128) ------------
   A [row][y] in smem (pitch apitch), B2 [y][24] basis in smem (pitch B2PITCH,
   cols 0..11 = cos, 12..23 = -sin). Output T rows at tbase + row*tstride,
   each row: 12 float2 (re at 2*ky, im at 2*ky+1). */
__device__ __forceinline__ void gemm_dfty(const float* A, int apitch, const float* B2,
                                          int m0,int g,int t4,
                                          float* tbase, int tstride){
    float acc2[3][4];
    #pragma unroll
    for(int nt=0;nt<3;nt++){ acc2[nt][0]=0.f;acc2[nt][1]=0.f;acc2[nt][2]=0.f;acc2[nt][3]=0.f; }
    #pragma unroll 1
    for(int kk=0;kk<16;kk++){
        int kb=kk*8;
        float af0=A[(m0+g)*apitch+kb+t4];
        float af1=A[(m0+8+g)*apitch+kb+t4];
        float af2=A[(m0+g)*apitch+kb+4+t4];
        float af3=A[(m0+8+g)*apitch+kb+4+t4];
        unsigned ah0=f2tf(af0), al0=f2tf(af0-__uint_as_float(ah0));
        unsigned ah1=f2tf(af1), al1=f2tf(af1-__uint_as_float(ah1));
        unsigned ah2=f2tf(af2), al2=f2tf(af2-__uint_as_float(ah2));
        unsigned ah3=f2tf(af3), al3=f2tf(af3-__uint_as_float(ah3));
        #pragma unroll
        for(int nt=0;nt<3;nt++){
            float bf0=B2[(kb+t4)*B2PITCH + nt*8 + g];
            float bf1=B2[(kb+4+t4)*B2PITCH + nt*8 + g];
            unsigned bh0=f2tf(bf0), bl0=f2tf(bf0-__uint_as_float(bh0));
            unsigned bh1=f2tf(bf1), bl1=f2tf(bf1-__uint_as_float(bh1));
            mma_tf32(acc2[nt], ah0,ah1,ah2,ah3, bh0,bh1);
            mma_tf32(acc2[nt], al0,al1,al2,al3, bh0,bh1);
            mma_tf32(acc2[nt], ah0,ah1,ah2,ah3, bl0,bl1);
        }
    }
    #pragma unroll
    for(int nt=0;nt<3;nt++){
        #pragma unroll
        for(int rr=0;rr<2;rr++){
            int o = m0 + rr*8 + g;
            float* Tf = tbase + (size_t)o*tstride;
            #pragma unroll
            for(int cc=0;cc<2;cc++){
                int col = nt*8 + 2*t4 + cc;
                int ky = (col<12)? col : col-12;
                int im = (col<12)? 0 : 1;
                Tf[ky*2+im] = acc2[nt][rr*2+cc];
            }
        }
    }
}

/* ------------ K1 standalone (layer 0): 64 consecutive (bc,x) rows per block ----- */
__global__ void __launch_bounds__(128) k1_mma(){
    float* sD  = sm;                 /* 64*DPITCH */
    float* sB2 = sm + 64*DPITCH;     /* 128*B2PITCH */
    int blk = blockIdx.x;
    int tid = threadIdx.x;
    const float* src = g_x + (size_t)blk*64*128;
    for(int i=tid;i<64*32;i+=128){
        int r=i>>5, yq=i&31;
        float4 v = ((const float4*)(src + r*128))[yq];
        float* d = sD + r*DPITCH + yq*4;
        d[0]=v.x; d[1]=v.y; d[2]=v.z; d[3]=v.w;
    }
    for(int i=tid;i<12*128;i+=128){
        int ky=i>>7, y=i&127;
        float2 e = g_By[i];
        sB2[y*B2PITCH + ky]      = e.x;
        sB2[y*B2PITCH + 12 + ky] = -e.y;
    }
    __syncthreads();
    int lane = tid&31, w = tid>>5;
    gemm_dfty(sD, DPITCH, sB2, w*16, lane>>2, lane&3,
              (float*)g_Ty + (size_t)blk*64*24, 24);
}

/* ------------ K2: DFT along x at 24 modes ------------ */
__global__ void k2_dftx(){
    __shared__ float2 sT[128*12];
    __shared__ float2 sb[24*129];
    int bc = blockIdx.x;
    const float2* tp = g_Ty + (size_t)bc*1536;
    for(int i=threadIdx.x;i<1536;i+=288) sT[i]=tp[i];
    for(int i=threadIdx.x;i<24*128;i+=288){ int kx=i>>7,x=i&127; sb[kx*129+x]=g_Bx[i]; }
    __syncthreads();
    int kx = threadIdx.x/12;
    int ky = threadIdx.x - kx*12;
    float are=0.f, aim=0.f;
    #pragma unroll 4
    for(int x=0;x<128;x++){
        float2 t = sT[x*12+ky];
        float2 e = sb[kx*129+x];
        are += t.x*e.x + t.y*e.y;
        aim += t.y*e.x - t.x*e.y;
    }
    g_modes[(size_t)bc*NMODE + kx*12 + ky] = make_float2(are,aim);
}

/* ------------ K3: per-mode complex 64x64 mix ------------ */
__global__ void k3_specmul(const float* __restrict__ w1r, const float* __restrict__ w1i,
                           const float* __restrict__ w2r, const float* __restrict__ w2i){
    __shared__ float2 sW[4096];
    __shared__ float2 sM[2048];
    int m  = blockIdx.x>>1;
    int bh = blockIdx.x&1;
    int kx = m/12, ky = m - kx*12;
    const float *wr, *wi; int kxw;
    if(kx<12){ wr=w1r; wi=w1i; kxw=kx; } else { wr=w2r; wi=w2i; kxw=kx-12; }
    int wofs = kxw*12+ky;
    for(int i=threadIdx.x;i<4096;i+=256)
        sW[i] = make_float2(wr[i*144+wofs], wi[i*144+wofs]);
    for(int i=threadIdx.x;i<2048;i+=256){
        int bl=i>>6, c=i&63;
        sM[i] = g_modes[((size_t)((bh*32+bl)*64+c))*NMODE + m];
    }
    __syncthreads();
    for(int k=0;k<8;k++){
        int idx = threadIdx.x + k*256;
        int bl = idx>>6, o = idx&63;
        float are=0.f, aim=0.f;
        #pragma unroll 4
        for(int i=0;i<64;i++){
            float2 mv=sM[bl*64+i];
            float2 wv=sW[i*64+o];
            are += mv.x*wv.x - mv.y*wv.y;
            aim += mv.x*wv.y + mv.y*wv.x;
        }
        g_omodes[((size_t)((bh*32+bl)*64+o))*NMODE + m] = make_float2(are,aim);
    }
}

/* ------------ K4: inverse DFT along x ------------ */
__global__ void k4_invx(){
    __shared__ float2 sO[288];
    __shared__ float2 sb[24*129];
    int bc = blockIdx.x;
    const float2* op = g_omodes + (size_t)bc*NMODE;
    for(int i=threadIdx.x;i<288;i+=384) sO[i]=op[i];
    for(int i=threadIdx.x;i<24*128;i+=384){ int kx=i>>7,x=i&127; sb[kx*129+x]=g_Bx[i]; }
    __syncthreads();
    int xb = threadIdx.x/12;
    int ky = threadIdx.x - xb*12;
    float scale = (ky==0 ? 1.f : 2.f)*(1.f/16384.f);
    for(int j=0;j<4;j++){
        int x = xb + 32*j;
        float are=0.f, aim=0.f;
        #pragma unroll
        for(int kx=0;kx<24;kx++){
            float2 o = sO[kx*12+ky];
            float2 e = sb[kx*129+x];
            are += o.x*e.x - o.y*e.y;
            aim += o.x*e.y + o.y*e.x;
        }
        g_U[((size_t)bc*128+x)*12+ky] = make_float2(are*scale, aim*scale);
    }
}

/* ------------ K5 fused tensor kernel:
   out[o][y] = W@X + inv-y spectral + bias  (one tf32 GEMM, K=96)
   then GELU -> g_x, then forward y-DFT of the result -> g_Ty (next layer). */
__global__ void __launch_bounds__(128) k5_mma(const float* __restrict__ pw,
                                              const float* __restrict__ pwb){
    float* sA   = sm;                       /* 64*APITCH  = 6400  */
    float* sB   = sm + 64*APITCH;           /* 96*BPITCH  = 13056 */
    float* sB2  = sm + 64*APITCH + 96*BPITCH; /* 128*B2PITCH = 5120 */
    float* outS = sB;                       /* reuse after GEMM1 */

    int b = blockIdx.x >> 7;
    int x = blockIdx.x & 127;
    int tid = threadIdx.x;

    /* A' : [o][k]  k<64:W, 64..75:Ure, 76..87:Uim, 88:bias, 89..95:0 */
    for(int i=tid;i<64*64;i+=128){
        int o=i>>6, c=i&63;
        sA[o*APITCH + c] = pw[i];
    }
    for(int i=tid;i<64*12;i+=128){
        int o=i/12, ky=i-o*12;
        float2 u = g_U[(((size_t)(b*64+o))*128+x)*12+ky];
        sA[o*APITCH + 64 + ky] = u.x;
        sA[o*APITCH + 76 + ky] = u.y;
    }
    for(int i=tid;i<64*8;i+=128){
        int o=i>>3, j=i&7;
        sA[o*APITCH + 88 + j] = (j==0)? pwb[o] : 0.f;
    }
    /* B' rows 0..63 = X[c][y] */
    for(int i=tid;i<64*32;i+=128){
        int c=i>>5, yq=i&31;
        float4 v = ((const float4*)(g_x + ((((size_t)(b*64+c))*128+x)<<7)))[yq];
        float* d = sB + c*BPITCH + yq*4;
        d[0]=v.x; d[1]=v.y; d[2]=v.z; d[3]=v.w;
    }
    /* B' rows 64..95 : cos / -sin / ones / zeros */
    for(int i=tid;i<32*128;i+=128){
        int r=i>>7, y=i&127;
        float v;
        if(r<12)       v =  g_By[r*128+y].x;
        else if(r<24)  v = -g_By[(r-12)*128+y].y;
        else if(r==24) v = 1.f;
        else           v = 0.f;
        sB[(64+r)*BPITCH + y] = v;
    }
    /* forward basis */
    for(int i=tid;i<12*128;i+=128){
        int ky=i>>7, y=i&127;
        float2 e = g_By[i];
        sB2[y*B2PITCH + ky]      = e.x;
        sB2[y*B2PITCH + 12 + ky] = -e.y;
    }
    __syncthreads();

    int lane = tid&31, w = tid>>5;
    int m0 = w*16, g = lane>>2, t4 = lane&3;

    float acc[16][4];
    #pragma unroll
    for(int nt=0;nt<16;nt++){ acc[nt][0]=0.f;acc[nt][1]=0.f;acc[nt][2]=0.f;acc[nt][3]=0.f; }

    #pragma unroll 1
    for(int kk=0;kk<12;kk++){
        int kb = kk*8;
        float af0=sA[(m0+g)*APITCH + kb + t4];
        float af1=sA[(m0+8+g)*APITCH + kb + t4];
        float af2=sA[(m0+g)*APITCH + kb + 4 + t4];
        float af3=sA[(m0+8+g)*APITCH + kb + 4 + t4];
        unsigned ah0=f2tf(af0), al0=f2tf(af0-__uint_as_float(ah0));
        unsigned ah1=f2tf(af1), al1=f2tf(af1-__uint_as_float(ah1));
        unsigned ah2=f2tf(af2), al2=f2tf(af2-__uint_as_float(ah2));
        unsigned ah3=f2tf(af3), al3=f2tf(af3-__uint_as_float(ah3));
        #pragma unroll
        for(int nt=0;nt<16;nt++){
            float bf0 = sB[(kb+t4)*BPITCH + nt*8 + g];
            float bf1 = sB[(kb+4+t4)*BPITCH + nt*8 + g];
            unsigned bh0=f2tf(bf0), bl0=f2tf(bf0-__uint_as_float(bh0));
            unsigned bh1=f2tf(bf1), bl1=f2tf(bf1-__uint_as_float(bh1));
            mma_tf32(acc[nt], ah0,ah1,ah2,ah3, bh0,bh1);
            mma_tf32(acc[nt], al0,al1,al2,al3, bh0,bh1);
            mma_tf32(acc[nt], ah0,ah1,ah2,ah3, bl0,bl1);
        }
    }
    __syncthreads();   /* everyone done reading sA/sB */

    /* GELU -> outS (overlaps sB) */
    #pragma unroll
    for(int nt=0;nt<16;nt++){
        int y0 = nt*8 + 2*t4;
        outS[(m0+g)*BPITCH + y0]     = gelu_f(acc[nt][0]);
        outS[(m0+g)*BPITCH + y0+1]   = gelu_f(acc[nt][1]);
        outS[(m0+8+g)*BPITCH + y0]   = gelu_f(acc[nt][2]);
        outS[(m0+8+g)*BPITCH + y0+1] = gelu_f(acc[nt][3]);
    }
    __syncthreads();

    /* coalesced store of x for next layer / final */
    for(int i=tid;i<64*32;i+=128){
        int c=i>>5, yq=i&31;
        const float* s = outS + c*BPITCH + yq*4;
        float4 v; v.x=s[0]; v.y=s[1]; v.z=s[2]; v.w=s[3];
        ((float4*)(g_x + ((((size_t)(b*64+c))*128+x)<<7)))[yq]=v;
    }

    /* fused next-layer forward y-DFT */
    gemm_dfty(outS, BPITCH, sB2, m0, g, t4,
              (float*)g_Ty + ((size_t)b*64*128 + x)*24, 128*24);
}

/* ------------ final ------------ */
__global__ void k_final(const float* __restrict__ xyt,
                        const float* __restrict__ pw, const float* __restrict__ pwb,
                        const float* __restrict__ fc1w, const float* __restrict__ fc1b,
                        const float* __restrict__ fc2w, const float* __restrict__ fc2b,
                        const int* __restrict__ Lxp, const int* __restrict__ Lyp,
                        float* __restrict__ out){
    __shared__ float  sXv[64];
    __shared__ float2 sPh[288];
    __shared__ float  sPart[128];
    __shared__ float  sY3[64];
    __shared__ float  sH[128];
    int b = blockIdx.x;
    int t = threadIdx.x;

    int rlx = Lxp[0], rly = Lyp[0];
    float Lx = (rlx>0 && rlx<(1<<23)) ? (float)rlx : __int_as_float(rlx);
    float Ly = (rly>0 && rly<(1<<23)) ? (float)rly : __int_as_float(rly);
    float qx = xyt[b*3+0], qy = xyt[b*3+1];
    float x01 = fminf(fmaxf(qx/fmaxf(Lx,1e-6f),0.f),1.f);
    float y01 = fminf(fmaxf(qy/fmaxf(Ly,1e-6f),0.f),1.f);
    float gx = x01*127.f, gy = y01*127.f;
    int x0 = (int)floorf(gx), y0 = (int)floorf(gy);
    int x1 = min(x0+1,127),  y1 = min(y0+1,127);
    float wx = gx-(float)x0, wy = gy-(float)y0;

    float outAcc = 0.f;

    for(int p=0;p<4;p++){
        int ix = p&1, iy = p>>1;
        int px = ix? x1:x0;
        int py = iy? y1:y0;
        float wgt = (ix? wx : 1.f-wx)*(iy? wy : 1.f-wy);

        for(int m=t;m<288;m+=128){
            int kx=m/12, ky=m-kx*12;
            int kg = kx<12 ? kx : kx+104;
            int mm = (kg*px + ky*py)&127;
            float a = (float)mm*(6.2831853071795864769f/128.f);
            float sv,cv; sincosf(a,&sv,&cv);
            float sc = (ky==0?1.f:2.f)*(1.f/16384.f);
            sPh[m] = make_float2(cv*sc, sv*sc);
        }
        if(t<64) sXv[t] = g_x[((((size_t)(b*64+t))*128+px)<<7)+py];
        __syncthreads();
        {
            int o = t&63, h = t>>6;
            const float2* op = g_omodes + (size_t)(b*64+o)*288 + h*144;
            const float2* ph = sPh + h*144;
            float acc=0.f;
            #pragma unroll 4
            for(int m=0;m<144;m++){
                float2 z=op[m]; float2 e=ph[m];
                acc += z.x*e.x - z.y*e.y;
            }
            sPart[t]=acc;
        }
        __syncthreads();
        if(t<64){
            float v = sPart[t]+sPart[t+64];
            float a = pwb[t];
            #pragma unroll 4
            for(int c=0;c<64;c++) a += sXv[c]*pw[t*64+c];
            sY3[t] = v + a;
        }
        __syncthreads();
        {
            float a = fc1b[t];
            #pragma unroll 4
            for(int o=0;o<64;o++) a += sY3[o]*fc1w[o*128+t];
            sH[t] = gelu_f(a);
        }
        __syncthreads();
        if(t<3){
            float a = fc2b[t];
            #pragma unroll 4
            for(int f=0;f<128;f++) a += sH[f]*fc2w[f*3+t];
            outAcc += wgt*a;
        }
        __syncthreads();
    }
    if(t<3) out[b*3+t]=outAcc;
}

/* ------------ launch ------------ */
extern "C" void kernel_launch(void* const* d_in, const int* in_sizes, int n_in,
                              void* d_out, int out_size){
    const float* xyt   = (const float*)d_in[0];
    const float* oc    = (const float*)d_in[1];
    const float* ov    = (const float*)d_in[2];
    const float* xg    = (const float*)d_in[3];
    const float* yg    = (const float*)d_in[4];
    const float* fc0w  = (const float*)d_in[5];
    const float* fc0b  = (const float*)d_in[6];
    const float* w1r   = (const float*)d_in[7];
    const float* w1i   = (const float*)d_in[8];
    const float* w2r   = (const float*)d_in[9];
    const float* w2i   = (const float*)d_in[10];
    const float* pww   = (const float*)d_in[11];
    const float* pwb   = (const float*)d_in[12];
    const float* fc1w  = (const float*)d_in[13];
    const float* fc1b  = (const float*)d_in[14];
    const float* fc2w  = (const float*)d_in[15];
    const float* fc2b  = (const float*)d_in[16];
    const int*   nb    = (const int*)d_in[17];
    const int*   siy   = (const int*)d_in[18];
    const int*   six   = (const int*)d_in[19];
    const int*   Lxp   = (const int*)d_in[20];
    const int*   Lyp   = (const int*)d_in[21];
    float* out = (float*)d_out;

    const int SM1 = (64*DPITCH + 128*B2PITCH)*4;                 /* k1_mma  */
    const int SM5 = (64*APITCH + 96*BPITCH + 128*B2PITCH)*4;     /* k5_mma  */
    cudaFuncSetAttribute(k1_mma, cudaFuncAttributeMaxDynamicSharedMemorySize, SM1);
    cudaFuncSetAttribute(k5_mma, cudaFuncAttributeMaxDynamicSharedMemorySize, SM5);

    k_basis<<<1,256>>>();
    k_zero<<<(BB*SS)/256,256>>>();
    k_scatter<<<1,64>>>(xyt,oc,ov,nb,siy,six);
    k_grid<<<(BB*SS)/256,256>>>();
    k_fc0<<<(BB*CC*SS)/256,256>>>(xg,yg,fc0w,fc0b);

    k1_mma<<<8192,128,SM1>>>();
    for(int L=0;L<4;L++){
        k2_dftx<<<BB*CC,288>>>();
        k3_specmul<<<NMODE*2,256>>>(w1r+(size_t)L*LWSTRIDE, w1i+(size_t)L*LWSTRIDE,
                                    w2r+(size_t)L*LWSTRIDE, w2i+(size_t)L*LWSTRIDE);
        if(L<3){
            k4_invx<<<BB*CC,384>>>();
            k5_mma<<<BB*NXX,128,SM5>>>(pww+(size_t)L*4096, pwb+(size_t)L*64);
        }
    }
    k_final<<<BB,128>>>(xyt, pww+3*4096, pwb+3*64,
                        fc1w, fc1b, fc2w, fc2b, Lxp, Lyp, out);
}